// round 12
// baseline (speedup 1.0000x reference)
#include <cuda_runtime.h>
#include <cstdint>

#define EN 200000
#define NN 25000
#define TILE 128
#define NTILES ((EN + TILE - 1) / TILE)   // 1563
#define ASTRIDE 68                        // words per A row (64 + 4 pad -> conflict-free frags)
#define A_WARP (32 * ASTRIDE)
#define SMEM_BYTES (4 * A_WARP * 4)       // 34816 B

typedef unsigned int uint;

// ---------------- scratch ----------------
__device__ float g_qs[NN * 8];
__device__ float g_qv[NN * 24];
__device__ float g_expv[EN];
__device__ float g_vbuf[32 * EN];
__device__ float g_zsum[NN];
__device__ float g_cnt[NN];
// B fragment image: flat index (((r*5+p)*8+t)*8+kb)*32+lane, float2 {b0,b1}
__device__ __align__(16) float2 g_bfrag[2 * 5 * 8 * 8 * 32];

__device__ __forceinline__ float to_tf32(float x) {
    uint r;
    asm("cvt.rna.tf32.f32 %0, %1;" : "=r"(r) : "f"(x));
    return __uint_as_float(r);
}

__device__ __forceinline__ void mma8(float c[4], const uint a[4], uint b0, uint b1) {
    asm("mma.sync.aligned.m16n8k8.row.col.f32.tf32.tf32.f32 "
        "{%0,%1,%2,%3}, {%4,%5,%6,%7}, {%8,%9}, {%0,%1,%2,%3};"
        : "+f"(c[0]), "+f"(c[1]), "+f"(c[2]), "+f"(c[3])
        : "r"(a[0]), "r"(a[1]), "r"(a[2]), "r"(a[3]), "r"(b0), "r"(b1));
}

// ---------------- kernel: W2 -> fragment-ordered B image (rna tf32) ----------------
__global__ void w2frag_kernel(const float* __restrict__ kW2, const float* __restrict__ vW2) {
    int idx = blockIdx.x * 256 + threadIdx.x;
    if (idx >= 2 * 5 * 8 * 8 * 32) return;
    int lane = idx & 31;
    int kb = (idx >> 5) & 7;
    int t  = (idx >> 8) & 7;
    int pr = idx >> 11;
    int p  = pr % 5;
    int r  = pr / 5;
    const float* W2 = r ? vW2 : kW2;
    int col = p * 64 + t * 8 + (lane >> 2);       // n-tile t == m index; n = lane>>2
    int k0 = kb * 8 + (lane & 3);
    float w0 = __ldg(W2 + k0 * 320 + col);
    float w1 = __ldg(W2 + (k0 + 4) * 320 + col);
    g_bfrag[idx] = make_float2(to_tf32(w0), to_tf32(w1));
}

// ---------------- kernel: zero init ----------------
__global__ void zero_kernel(float* __restrict__ out) {
    int i = blockIdx.x * blockDim.x + threadIdx.x;
    if (i < NN * 32) out[i] = 0.f;
    if (i < NN) { g_zsum[i] = 0.f; g_cnt[i] = 0.f; }
}

// ---------------- kernel: node projections qs, qv ----------------
__global__ void node_kernel(const float* __restrict__ node_attr,
                            const float* __restrict__ Wq0,
                            const float* __restrict__ Wq1)
{
    int n = blockIdx.x * blockDim.x + threadIdx.x;
    if (n >= NN) return;
    float na[32];
    const float4* p = reinterpret_cast<const float4*>(node_attr + (size_t)n * 32);
    #pragma unroll
    for (int q = 0; q < 8; q++) {
        float4 v = __ldg(p + q);
        na[4*q] = v.x; na[4*q+1] = v.y; na[4*q+2] = v.z; na[4*q+3] = v.w;
    }
    const float im = 0.35355339059327373f;
    #pragma unroll
    for (int k = 0; k < 8; k++) {
        float a = 0.f;
        #pragma unroll
        for (int m = 0; m < 8; m++) a = fmaf(na[m], __ldg(Wq0 + m * 8 + k), a);
        g_qs[n * 8 + k] = a * im;
    }
    #pragma unroll
    for (int k = 0; k < 8; k++) {
        float a0 = 0.f, a1 = 0.f, a2 = 0.f;
        #pragma unroll
        for (int m = 0; m < 8; m++) {
            float w = __ldg(Wq1 + m * 8 + k);
            a0 = fmaf(na[8 + 3*m],  w, a0);
            a1 = fmaf(na[9 + 3*m],  w, a1);
            a2 = fmaf(na[10 + 3*m], w, a2);
        }
        g_qv[n * 24 + 3*k]     = a0 * im;
        g_qv[n * 24 + 3*k + 1] = a1 * im;
        g_qv[n * 24 + 3*k + 2] = a2 * im;
    }
}

// ---------------- device helpers ----------------
__device__ __forceinline__ void compute_h(const float* __restrict__ W1,
                                          const float4* __restrict__ eap, float* h) {
    #pragma unroll
    for (int j = 0; j < 64; j++) h[j] = 0.f;
    #pragma unroll
    for (int qq = 0; qq < 4; qq++) {
        float4 eav = __ldg(eap + qq);
        float ea4[4] = {eav.x, eav.y, eav.z, eav.w};
        #pragma unroll
        for (int ii = 0; ii < 4; ii++) {
            float eai = ea4[ii];
            const float4* wp = reinterpret_cast<const float4*>(W1 + (4 * qq + ii) * 64);
            #pragma unroll
            for (int jq = 0; jq < 16; jq++) {
                float4 w = __ldg(wp + jq);
                h[4*jq+0] = fmaf(eai, w.x, h[4*jq+0]);
                h[4*jq+1] = fmaf(eai, w.y, h[4*jq+1]);
                h[4*jq+2] = fmaf(eai, w.z, h[4*jq+2]);
                h[4*jq+3] = fmaf(eai, w.w, h[4*jq+3]);
            }
        }
    }
    #pragma unroll
    for (int j = 0; j < 64; j++) {
        float s = h[j] * 0.25f;
        h[j] = __fdividef(s, 1.f + __expf(-s));
    }
}

// Contract a half-tile: acc[mt][..] += sum_{t4} C[mt][t4][..] * a[row][m=TH*4+t4]
__device__ __forceinline__ void contract_half(const float C[2][4][4], const float av4[4],
                                              int g, float acc[2][4]) {
    #pragma unroll
    for (int t4 = 0; t4 < 4; t4++) {
        float a = av4[t4];
        #pragma unroll
        for (int mt = 0; mt < 2; mt++) {
            float a0 = __shfl_sync(0xFFFFFFFFu, a, mt * 16 + g);
            float a1 = __shfl_sync(0xFFFFFFFFu, a, mt * 16 + g + 8);
            acc[mt][0] = fmaf(C[mt][t4][0], a0, acc[mt][0]);
            acc[mt][1] = fmaf(C[mt][t4][1], a0, acc[mt][1]);
            acc[mt][2] = fmaf(C[mt][t4][2], a1, acc[mt][2]);
            acc[mt][3] = fmaf(C[mt][t4][3], a1, acc[mt][3]);
        }
    }
}

// Gather fragment-space acc to edge-owner lane: out[n] for n=0..7 of this lane's edge
__device__ __forceinline__ void gather_comp(const float acc[2][4], int lane, float* out) {
    int r16 = lane & 15;
    int base = (r16 & 7) * 4;
    bool hm = lane >= 16, hr = r16 >= 8;
    #pragma unroll
    for (int j = 0; j < 4; j++) {
        int s = base + j;
        float v00 = __shfl_sync(0xFFFFFFFFu, acc[0][0], s);
        float v01 = __shfl_sync(0xFFFFFFFFu, acc[0][1], s);
        float v02 = __shfl_sync(0xFFFFFFFFu, acc[0][2], s);
        float v03 = __shfl_sync(0xFFFFFFFFu, acc[0][3], s);
        float v10 = __shfl_sync(0xFFFFFFFFu, acc[1][0], s);
        float v11 = __shfl_sync(0xFFFFFFFFu, acc[1][1], s);
        float v12 = __shfl_sync(0xFFFFFFFFu, acc[1][2], s);
        float v13 = __shfl_sync(0xFFFFFFFFu, acc[1][3], s);
        out[2*j]     = hm ? (hr ? v12 : v10) : (hr ? v02 : v00);
        out[2*j + 1] = hm ? (hr ? v13 : v11) : (hr ? v03 : v01);
    }
}

// ---------------- kernel: per-tile mma.sync edge compute (1-term rna tf32) ----------------
__global__ __launch_bounds__(128) void edge_mma_kernel(
    const float* __restrict__ node_attr, const int* __restrict__ ei,
    const float* __restrict__ edge_attr, const float* __restrict__ edge_sh,
    const float* __restrict__ kW1, const float* __restrict__ vW1,
    const float* __restrict__ Wd0, const float* __restrict__ Wd1)
{
    extern __shared__ float sA[];
    int tid = threadIdx.x;
    int lane = tid & 31;
    int wid = tid >> 5;
    int g = lane >> 2, q = lane & 3;
    int e = blockIdx.x * TILE + tid;
    bool active = e < EN;
    int ee = active ? e : 0;

    int src = __ldg(ei + ee);
    int dst = __ldg(ei + EN + ee);
    const float4* eap = reinterpret_cast<const float4*>(edge_attr + (size_t)ee * 16);

    float4 sh = __ldg(reinterpret_cast<const float4*>(edge_sh + (size_t)ee * 4));
    float s0 = sh.x, s1x = sh.y, s1y = sh.z, s1z = sh.w;
    const float i3 = 0.5773502691896258f;
    const float i2 = 0.7071067811865476f;
    float t3x = s1x * i3, t3y = s1y * i3, t3z = s1z * i3;
    float t2x = s1x * i2, t2y = s1y * i2, t2z = s1z * i2;

    float xs[8], vv[8][3];
    {
        const float4* p = reinterpret_cast<const float4*>(node_attr + (size_t)src * 32);
        float4 a0 = __ldg(p + 0), a1 = __ldg(p + 1);
        xs[0]=a0.x; xs[1]=a0.y; xs[2]=a0.z; xs[3]=a0.w;
        xs[4]=a1.x; xs[5]=a1.y; xs[6]=a1.z; xs[7]=a1.w;
        #pragma unroll
        for (int qq = 0; qq < 6; qq++) {
            float4 v = __ldg(p + 2 + qq);
            float* d = &vv[0][0] + 4 * qq;
            d[0]=v.x; d[1]=v.y; d[2]=v.z; d[3]=v.w;
        }
    }

    float* Ahi = sA + wid * A_WARP;

    const float c_s = 0.03125f;               // (1/8)*(1/sqrt(16))
    const float c_v = 0.025515518153991442f;  // (1/8)*(1/sqrt(24))

    #pragma unroll 1
    for (int r = 0; r < 2; r++) {
        // ---- h -> A (warp-local 32x64 tile, rna tf32) ----
        {
            float h[64];
            compute_h(r ? vW1 : kW1, eap, h);
            #pragma unroll
            for (int j = 0; j < 64; j++)
                Ahi[lane * ASTRIDE + j] = to_tf32(h[j]);
        }
        __syncthreads();

        float accS[2][4]   = {{0,0,0,0},{0,0,0,0}};
        float accT1[2][4]  = {{0,0,0,0},{0,0,0,0}};
        float accT24[3][2][4] = {{{0,0,0,0},{0,0,0,0}},{{0,0,0,0},{0,0,0,0}},{{0,0,0,0},{0,0,0,0}}};

        #pragma unroll 1
        for (int p = 0; p < 5; p++) {
            const float2* bp = g_bfrag + (size_t)((r * 5 + p) * 8) * 8 * 32;
            #pragma unroll
            for (int th = 0; th < 2; th++) {
                float C[2][4][4] = {};
                #pragma unroll 1
                for (int kb = 0; kb < 8; kb++) {
                    uint ah[2][4];
                    #pragma unroll
                    for (int mt = 0; mt < 2; mt++) {
                        const float* bh = Ahi + (mt * 16 + g) * ASTRIDE + kb * 8 + q;
                        ah[mt][0] = __float_as_uint(bh[0]);
                        ah[mt][1] = __float_as_uint(bh[8 * ASTRIDE]);
                        ah[mt][2] = __float_as_uint(bh[4]);
                        ah[mt][3] = __float_as_uint(bh[8 * ASTRIDE + 4]);
                    }
                    #pragma unroll
                    for (int t4 = 0; t4 < 4; t4++) {
                        int t = th * 4 + t4;
                        float2 b = __ldg(bp + (size_t)(t * 8 + kb) * 32 + lane);
                        uint b0 = __float_as_uint(b.x), b1 = __float_as_uint(b.y);
                        mma8(C[0][t4], ah[0], b0, b1);
                        mma8(C[1][t4], ah[1], b0, b1);
                    }
                }
                // ---- contract this half (m = th*4 + t4) ----
                float av[4];
                if (p == 0) {
                    #pragma unroll
                    for (int t4 = 0; t4 < 4; t4++) av[t4] = xs[th * 4 + t4] * s0;
                    contract_half(C, av, g, accS);
                } else if (p == 1) {
                    #pragma unroll
                    for (int t4 = 0; t4 < 4; t4++) av[t4] = xs[th * 4 + t4];
                    contract_half(C, av, g, accT1);
                } else if (p == 2) {
                    #pragma unroll
                    for (int c = 0; c < 3; c++) {
                        #pragma unroll
                        for (int t4 = 0; t4 < 4; t4++) av[t4] = vv[th * 4 + t4][c] * s0;
                        contract_half(C, av, g, accT24[c]);
                    }
                } else if (p == 3) {
                    #pragma unroll
                    for (int t4 = 0; t4 < 4; t4++) {
                        int m = th * 4 + t4;
                        av[t4] = vv[m][0] * t3x + vv[m][1] * t3y + vv[m][2] * t3z;
                    }
                    contract_half(C, av, g, accS);
                } else {
                    #pragma unroll
                    for (int t4 = 0; t4 < 4; t4++) {
                        int m = th * 4 + t4;
                        av[t4] = vv[m][1] * t2z - vv[m][2] * t2y;
                    }
                    contract_half(C, av, g, accT24[0]);
                    #pragma unroll
                    for (int t4 = 0; t4 < 4; t4++) {
                        int m = th * 4 + t4;
                        av[t4] = vv[m][2] * t2x - vv[m][0] * t2z;
                    }
                    contract_half(C, av, g, accT24[1]);
                    #pragma unroll
                    for (int t4 = 0; t4 < 4; t4++) {
                        int m = th * 4 + t4;
                        av[t4] = vv[m][0] * t2y - vv[m][1] * t2x;
                    }
                    contract_half(C, av, g, accT24[2]);
                }
            }
        }

        // ---- gather to edge-owner lanes ----
        float Sg[8], T1g[8], Tx[8], Ty[8], Tz[8];
        gather_comp(accS,      lane, Sg);
        gather_comp(accT1,     lane, T1g);
        gather_comp(accT24[0], lane, Tx);
        gather_comp(accT24[1], lane, Ty);
        gather_comp(accT24[2], lane, Tz);

        if (r == 0) {
            // ---- K radial: ks/kv -> logits ----
            float ks[8], kv[8][3];
            #pragma unroll
            for (int n = 0; n < 8; n++) {
                ks[n]    = Sg[n] * c_s;
                kv[n][0] = (T1g[n] * s1x + Tx[n]) * c_v;
                kv[n][1] = (T1g[n] * s1y + Ty[n]) * c_v;
                kv[n][2] = (T1g[n] * s1z + Tz[n]) * c_v;
            }
            float qsd[8], qvd[24];
            {
                const float4* p = reinterpret_cast<const float4*>(g_qs + (size_t)dst * 8);
                float4 a = p[0], bq = p[1];
                qsd[0]=a.x; qsd[1]=a.y; qsd[2]=a.z; qsd[3]=a.w;
                qsd[4]=bq.x; qsd[5]=bq.y; qsd[6]=bq.z; qsd[7]=bq.w;
            }
            {
                const float4* p = reinterpret_cast<const float4*>(g_qv + (size_t)dst * 24);
                #pragma unroll
                for (int qq = 0; qq < 6; qq++) {
                    float4 v = p[qq];
                    qvd[4*qq]=v.x; qvd[4*qq+1]=v.y; qvd[4*qq+2]=v.z; qvd[4*qq+3]=v.w;
                }
            }
            float t0 = 0.f, t1 = 0.f;
            #pragma unroll
            for (int m = 0; m < 8; m++) {
                float rr = 0.f;
                #pragma unroll
                for (int n = 0; n < 8; n++) rr = fmaf(__ldg(Wd0 + m * 8 + n), ks[n], rr);
                t0 = fmaf(qsd[m], rr, t0);
            }
            #pragma unroll
            for (int m = 0; m < 8; m++) {
                float rr = 0.f;
                #pragma unroll
                for (int n = 0; n < 8; n++) {
                    float dd = qvd[3*m] * kv[n][0] + qvd[3*m+1] * kv[n][1] + qvd[3*m+2] * kv[n][2];
                    rr = fmaf(__ldg(Wd1 + m * 8 + n), dd, rr);
                }
                t1 += rr;
            }
            float logit = (t0 + t1 * i3) * 0.25f;
            float ex = __expf(logit);
            if (active) {
                g_expv[e] = ex;
                atomicAdd(&g_zsum[dst], ex);
                atomicAdd(&g_cnt[dst], 1.f);
            }
        } else {
            // ---- V radial -> g_vbuf ----
            if (active) {
                #pragma unroll
                for (int n = 0; n < 8; n++) g_vbuf[n * EN + e] = Sg[n] * c_s;
                #pragma unroll
                for (int n = 0; n < 8; n++) {
                    g_vbuf[(8 + 3*n + 0) * EN + e] = (T1g[n] * s1x + Tx[n]) * c_v;
                    g_vbuf[(8 + 3*n + 1) * EN + e] = (T1g[n] * s1y + Ty[n]) * c_v;
                    g_vbuf[(8 + 3*n + 2) * EN + e] = (T1g[n] * s1z + Tz[n]) * c_v;
                }
            }
        }
        __syncthreads();   // A reused next radial
    }
}

// ---------------- kernel: normalize + scatter ----------------
__global__ void scatter_kernel(const int* __restrict__ ei, float* __restrict__ out) {
    int e = blockIdx.x * blockDim.x + threadIdx.x;
    if (e >= EN) return;
    int dst = __ldg(ei + EN + e);
    float ex = g_expv[e];
    float zs = g_zsum[dst];
    float c  = g_cnt[dst];
    float alpha = ex * fmaxf(c, 1.f) / zs;
    float attn = sqrtf(fmaxf(alpha, 0.f));
    float* op = out + (size_t)dst * 32;
    #pragma unroll
    for (int k = 0; k < 32; k++)
        atomicAdd(op + k, attn * g_vbuf[k * EN + e]);
}

// ---------------- launcher ----------------
extern "C" void kernel_launch(void* const* d_in, const int* in_sizes, int n_in,
                              void* d_out, int out_size) {
    const float* node_attr = (const float*)d_in[0];
    const int*   ei        = (const int*)  d_in[1];
    const float* edge_attr = (const float*)d_in[2];
    const float* edge_sh   = (const float*)d_in[3];
    const float* Wq0       = (const float*)d_in[4];
    const float* Wq1       = (const float*)d_in[5];
    const float* kW1       = (const float*)d_in[6];
    const float* kW2       = (const float*)d_in[7];
    const float* vW1       = (const float*)d_in[8];
    const float* vW2       = (const float*)d_in[9];
    const float* Wd0       = (const float*)d_in[10];
    const float* Wd1       = (const float*)d_in[11];
    float* out = (float*)d_out;

    static bool attr_set = false;
    if (!attr_set) {
        cudaFuncSetAttribute(edge_mma_kernel,
                             cudaFuncAttributeMaxDynamicSharedMemorySize, SMEM_BYTES);
        attr_set = true;
    }

    w2frag_kernel<<<(2 * 5 * 8 * 8 * 32 + 255) / 256, 256>>>(kW2, vW2);
    zero_kernel<<<(NN * 32 + 255) / 256, 256>>>(out);
    node_kernel<<<(NN + 127) / 128, 128>>>(node_attr, Wq0, Wq1);
    edge_mma_kernel<<<NTILES, TILE, SMEM_BYTES>>>(node_attr, ei, edge_attr, edge_sh,
                                                  kW1, vW1, Wd0, Wd1);
    scatter_kernel<<<(EN + 255) / 256, 256>>>(ei, out);
}

// round 16
// speedup vs baseline: 1.1587x; 1.1587x over previous
#include <cuda_runtime.h>
#include <cstdint>

#define EN 200000
#define NN 25000
#define TILE 128
#define NTILES ((EN + TILE - 1) / TILE)   // 1563
#define ASTRIDE 68                        // words per A row (64 + 4 pad -> conflict-free frags)
#define A_WARP (32 * ASTRIDE)
#define SMEM_BYTES (4 * A_WARP * 4)       // 34816 B

typedef unsigned int uint;

// ---------------- scratch ----------------
__device__ float g_qs[NN * 8];
__device__ float g_qv[NN * 24];
__device__ float g_expv[EN];
__device__ float g_vbuf[32 * EN];
__device__ float g_zsum[NN];
__device__ float g_cnt[NN];
// B fragment image: flat index (((r*5+p)*8+t)*8+kb)*32+lane, float2 {b0,b1}
__device__ __align__(16) float2 g_bfrag[2 * 5 * 8 * 8 * 32];

__device__ __forceinline__ float to_tf32(float x) {
    uint r;
    asm("cvt.rna.tf32.f32 %0, %1;" : "=r"(r) : "f"(x));
    return __uint_as_float(r);
}

__device__ __forceinline__ void mma8(float c[4], const uint a[4], uint b0, uint b1) {
    asm("mma.sync.aligned.m16n8k8.row.col.f32.tf32.tf32.f32 "
        "{%0,%1,%2,%3}, {%4,%5,%6,%7}, {%8,%9}, {%0,%1,%2,%3};"
        : "+f"(c[0]), "+f"(c[1]), "+f"(c[2]), "+f"(c[3])
        : "r"(a[0]), "r"(a[1]), "r"(a[2]), "r"(a[3]), "r"(b0), "r"(b1));
}

// ---------------- kernel: W2 -> fragment-ordered B image (rna tf32) ----------------
__global__ void w2frag_kernel(const float* __restrict__ kW2, const float* __restrict__ vW2) {
    int idx = blockIdx.x * 256 + threadIdx.x;
    if (idx >= 2 * 5 * 8 * 8 * 32) return;
    int lane = idx & 31;
    int kb = (idx >> 5) & 7;
    int t  = (idx >> 8) & 7;
    int pr = idx >> 11;
    int p  = pr % 5;
    int r  = pr / 5;
    const float* W2 = r ? vW2 : kW2;
    int col = p * 64 + t * 8 + (lane >> 2);       // n-tile t == m index; n = lane>>2
    int k0 = kb * 8 + (lane & 3);
    float w0 = __ldg(W2 + k0 * 320 + col);
    float w1 = __ldg(W2 + (k0 + 4) * 320 + col);
    g_bfrag[idx] = make_float2(to_tf32(w0), to_tf32(w1));
}

// ---------------- kernel: zero init ----------------
__global__ void zero_kernel(float* __restrict__ out) {
    int i = blockIdx.x * blockDim.x + threadIdx.x;
    if (i < NN * 32) out[i] = 0.f;
    if (i < NN) { g_zsum[i] = 0.f; g_cnt[i] = 0.f; }
}

// ---------------- kernel: node projections qs, qv ----------------
__global__ void node_kernel(const float* __restrict__ node_attr,
                            const float* __restrict__ Wq0,
                            const float* __restrict__ Wq1)
{
    int n = blockIdx.x * blockDim.x + threadIdx.x;
    if (n >= NN) return;
    float na[32];
    const float4* p = reinterpret_cast<const float4*>(node_attr + (size_t)n * 32);
    #pragma unroll
    for (int q = 0; q < 8; q++) {
        float4 v = __ldg(p + q);
        na[4*q] = v.x; na[4*q+1] = v.y; na[4*q+2] = v.z; na[4*q+3] = v.w;
    }
    const float im = 0.35355339059327373f;
    #pragma unroll
    for (int k = 0; k < 8; k++) {
        float a = 0.f;
        #pragma unroll
        for (int m = 0; m < 8; m++) a = fmaf(na[m], __ldg(Wq0 + m * 8 + k), a);
        g_qs[n * 8 + k] = a * im;
    }
    #pragma unroll
    for (int k = 0; k < 8; k++) {
        float a0 = 0.f, a1 = 0.f, a2 = 0.f;
        #pragma unroll
        for (int m = 0; m < 8; m++) {
            float w = __ldg(Wq1 + m * 8 + k);
            a0 = fmaf(na[8 + 3*m],  w, a0);
            a1 = fmaf(na[9 + 3*m],  w, a1);
            a2 = fmaf(na[10 + 3*m], w, a2);
        }
        g_qv[n * 24 + 3*k]     = a0 * im;
        g_qv[n * 24 + 3*k + 1] = a1 * im;
        g_qv[n * 24 + 3*k + 2] = a2 * im;
    }
}

// ---------------- device helpers ----------------
__device__ __forceinline__ void compute_h(const float* __restrict__ W1,
                                          const float4* __restrict__ eap, float* h) {
    #pragma unroll
    for (int j = 0; j < 64; j++) h[j] = 0.f;
    #pragma unroll
    for (int qq = 0; qq < 4; qq++) {
        float4 eav = __ldg(eap + qq);
        float ea4[4] = {eav.x, eav.y, eav.z, eav.w};
        #pragma unroll
        for (int ii = 0; ii < 4; ii++) {
            float eai = ea4[ii];
            const float4* wp = reinterpret_cast<const float4*>(W1 + (4 * qq + ii) * 64);
            #pragma unroll
            for (int jq = 0; jq < 16; jq++) {
                float4 w = __ldg(wp + jq);
                h[4*jq+0] = fmaf(eai, w.x, h[4*jq+0]);
                h[4*jq+1] = fmaf(eai, w.y, h[4*jq+1]);
                h[4*jq+2] = fmaf(eai, w.z, h[4*jq+2]);
                h[4*jq+3] = fmaf(eai, w.w, h[4*jq+3]);
            }
        }
    }
    #pragma unroll
    for (int j = 0; j < 64; j++) {
        float s = h[j] * 0.25f;
        h[j] = __fdividef(s, 1.f + __expf(-s));
    }
}

// Contract a half-tile: acc[mt][..] += sum_{t4} C[mt][t4][..] * a[row][m=TH*4+t4]
__device__ __forceinline__ void contract_half(const float C[2][4][4], const float av4[4],
                                              int g, float acc[2][4]) {
    #pragma unroll
    for (int t4 = 0; t4 < 4; t4++) {
        float a = av4[t4];
        #pragma unroll
        for (int mt = 0; mt < 2; mt++) {
            float a0 = __shfl_sync(0xFFFFFFFFu, a, mt * 16 + g);
            float a1 = __shfl_sync(0xFFFFFFFFu, a, mt * 16 + g + 8);
            acc[mt][0] = fmaf(C[mt][t4][0], a0, acc[mt][0]);
            acc[mt][1] = fmaf(C[mt][t4][1], a0, acc[mt][1]);
            acc[mt][2] = fmaf(C[mt][t4][2], a1, acc[mt][2]);
            acc[mt][3] = fmaf(C[mt][t4][3], a1, acc[mt][3]);
        }
    }
}

// Gather fragment-space acc to edge-owner lane: out[n] for n=0..7 of this lane's edge
__device__ __forceinline__ void gather_comp(const float acc[2][4], int lane, float* out) {
    int r16 = lane & 15;
    int base = (r16 & 7) * 4;
    bool hm = lane >= 16, hr = r16 >= 8;
    #pragma unroll
    for (int j = 0; j < 4; j++) {
        int s = base + j;
        float v00 = __shfl_sync(0xFFFFFFFFu, acc[0][0], s);
        float v01 = __shfl_sync(0xFFFFFFFFu, acc[0][1], s);
        float v02 = __shfl_sync(0xFFFFFFFFu, acc[0][2], s);
        float v03 = __shfl_sync(0xFFFFFFFFu, acc[0][3], s);
        float v10 = __shfl_sync(0xFFFFFFFFu, acc[1][0], s);
        float v11 = __shfl_sync(0xFFFFFFFFu, acc[1][1], s);
        float v12 = __shfl_sync(0xFFFFFFFFu, acc[1][2], s);
        float v13 = __shfl_sync(0xFFFFFFFFu, acc[1][3], s);
        out[2*j]     = hm ? (hr ? v12 : v10) : (hr ? v02 : v00);
        out[2*j + 1] = hm ? (hr ? v13 : v11) : (hr ? v03 : v01);
    }
}

// ---------------- kernel: per-tile mma.sync edge compute (1-term rna tf32) ----------------
__global__ __launch_bounds__(128, 3) void edge_mma_kernel(
    const float* __restrict__ node_attr, const int* __restrict__ ei,
    const float* __restrict__ edge_attr, const float* __restrict__ edge_sh,
    const float* __restrict__ kW1, const float* __restrict__ vW1,
    const float* __restrict__ Wd0, const float* __restrict__ Wd1)
{
    extern __shared__ float sA[];
    int tid = threadIdx.x;
    int lane = tid & 31;
    int wid = tid >> 5;
    int g = lane >> 2, q = lane & 3;
    int e = blockIdx.x * TILE + tid;
    bool active = e < EN;
    int ee = active ? e : 0;

    int src = __ldg(ei + ee);
    int dst = __ldg(ei + EN + ee);
    const float4* eap = reinterpret_cast<const float4*>(edge_attr + (size_t)ee * 16);

    float4 sh = __ldg(reinterpret_cast<const float4*>(edge_sh + (size_t)ee * 4));
    float s0 = sh.x, s1x = sh.y, s1y = sh.z, s1z = sh.w;
    const float i3 = 0.5773502691896258f;
    const float i2 = 0.7071067811865476f;
    float t3x = s1x * i3, t3y = s1y * i3, t3z = s1z * i3;
    float t2x = s1x * i2, t2y = s1y * i2, t2z = s1z * i2;

    float xs[8], vv[8][3];
    {
        const float4* p = reinterpret_cast<const float4*>(node_attr + (size_t)src * 32);
        float4 a0 = __ldg(p + 0), a1 = __ldg(p + 1);
        xs[0]=a0.x; xs[1]=a0.y; xs[2]=a0.z; xs[3]=a0.w;
        xs[4]=a1.x; xs[5]=a1.y; xs[6]=a1.z; xs[7]=a1.w;
        #pragma unroll
        for (int qq = 0; qq < 6; qq++) {
            float4 v = __ldg(p + 2 + qq);
            float* d = &vv[0][0] + 4 * qq;
            d[0]=v.x; d[1]=v.y; d[2]=v.z; d[3]=v.w;
        }
    }

    float* Ahi = sA + wid * A_WARP;

    const float c_s = 0.03125f;               // (1/8)*(1/sqrt(16))
    const float c_v = 0.025515518153991442f;  // (1/8)*(1/sqrt(24))

    #pragma unroll 1
    for (int r = 0; r < 2; r++) {
        // ---- h -> A (warp-local 32x64 tile, rna tf32) ----
        {
            float h[64];
            compute_h(r ? vW1 : kW1, eap, h);
            #pragma unroll
            for (int j = 0; j < 64; j++)
                Ahi[lane * ASTRIDE + j] = to_tf32(h[j]);
        }
        __syncthreads();

        float accS[2][4]   = {{0,0,0,0},{0,0,0,0}};
        float accT1[2][4]  = {{0,0,0,0},{0,0,0,0}};
        float accT24[3][2][4] = {{{0,0,0,0},{0,0,0,0}},{{0,0,0,0},{0,0,0,0}},{{0,0,0,0},{0,0,0,0}}};

        #pragma unroll 1
        for (int p = 0; p < 5; p++) {
            const float2* bp = g_bfrag + (size_t)((r * 5 + p) * 8) * 8 * 32;
            #pragma unroll
            for (int th = 0; th < 2; th++) {
                float C[2][4][4] = {};
                // prefetch kb=0 B fragments
                float2 bcur[4];
                #pragma unroll
                for (int t4 = 0; t4 < 4; t4++) {
                    int t = th * 4 + t4;
                    bcur[t4] = __ldg(bp + (size_t)(t * 8 + 0) * 32 + lane);
                }
                #pragma unroll 1
                for (int kb = 0; kb < 8; kb++) {
                    uint ah[2][4];
                    #pragma unroll
                    for (int mt = 0; mt < 2; mt++) {
                        const float* bh = Ahi + (mt * 16 + g) * ASTRIDE + kb * 8 + q;
                        ah[mt][0] = __float_as_uint(bh[0]);
                        ah[mt][1] = __float_as_uint(bh[8 * ASTRIDE]);
                        ah[mt][2] = __float_as_uint(bh[4]);
                        ah[mt][3] = __float_as_uint(bh[8 * ASTRIDE + 4]);
                    }
                    // prefetch next kb's B fragments before issuing MMAs
                    float2 bnext[4];
                    if (kb < 7) {
                        #pragma unroll
                        for (int t4 = 0; t4 < 4; t4++) {
                            int t = th * 4 + t4;
                            bnext[t4] = __ldg(bp + (size_t)(t * 8 + kb + 1) * 32 + lane);
                        }
                    }
                    #pragma unroll
                    for (int t4 = 0; t4 < 4; t4++) {
                        uint b0 = __float_as_uint(bcur[t4].x), b1 = __float_as_uint(bcur[t4].y);
                        mma8(C[0][t4], ah[0], b0, b1);
                        mma8(C[1][t4], ah[1], b0, b1);
                    }
                    if (kb < 7) {
                        #pragma unroll
                        for (int t4 = 0; t4 < 4; t4++) bcur[t4] = bnext[t4];
                    }
                }
                // ---- contract this half (m = th*4 + t4) ----
                float av[4];
                if (p == 0) {
                    #pragma unroll
                    for (int t4 = 0; t4 < 4; t4++) av[t4] = xs[th * 4 + t4] * s0;
                    contract_half(C, av, g, accS);
                } else if (p == 1) {
                    #pragma unroll
                    for (int t4 = 0; t4 < 4; t4++) av[t4] = xs[th * 4 + t4];
                    contract_half(C, av, g, accT1);
                } else if (p == 2) {
                    #pragma unroll
                    for (int c = 0; c < 3; c++) {
                        #pragma unroll
                        for (int t4 = 0; t4 < 4; t4++) av[t4] = vv[th * 4 + t4][c] * s0;
                        contract_half(C, av, g, accT24[c]);
                    }
                } else if (p == 3) {
                    #pragma unroll
                    for (int t4 = 0; t4 < 4; t4++) {
                        int m = th * 4 + t4;
                        av[t4] = vv[m][0] * t3x + vv[m][1] * t3y + vv[m][2] * t3z;
                    }
                    contract_half(C, av, g, accS);
                } else {
                    #pragma unroll
                    for (int t4 = 0; t4 < 4; t4++) {
                        int m = th * 4 + t4;
                        av[t4] = vv[m][1] * t2z - vv[m][2] * t2y;
                    }
                    contract_half(C, av, g, accT24[0]);
                    #pragma unroll
                    for (int t4 = 0; t4 < 4; t4++) {
                        int m = th * 4 + t4;
                        av[t4] = vv[m][2] * t2x - vv[m][0] * t2z;
                    }
                    contract_half(C, av, g, accT24[1]);
                    #pragma unroll
                    for (int t4 = 0; t4 < 4; t4++) {
                        int m = th * 4 + t4;
                        av[t4] = vv[m][0] * t2y - vv[m][1] * t2x;
                    }
                    contract_half(C, av, g, accT24[2]);
                }
            }
        }

        // ---- gather to edge-owner lanes ----
        float Sg[8], T1g[8], Tx[8], Ty[8], Tz[8];
        gather_comp(accS,      lane, Sg);
        gather_comp(accT1,     lane, T1g);
        gather_comp(accT24[0], lane, Tx);
        gather_comp(accT24[1], lane, Ty);
        gather_comp(accT24[2], lane, Tz);

        if (r == 0) {
            // ---- K radial: ks/kv -> logits ----
            float ks[8], kv[8][3];
            #pragma unroll
            for (int n = 0; n < 8; n++) {
                ks[n]    = Sg[n] * c_s;
                kv[n][0] = (T1g[n] * s1x + Tx[n]) * c_v;
                kv[n][1] = (T1g[n] * s1y + Ty[n]) * c_v;
                kv[n][2] = (T1g[n] * s1z + Tz[n]) * c_v;
            }
            float qsd[8], qvd[24];
            {
                const float4* p = reinterpret_cast<const float4*>(g_qs + (size_t)dst * 8);
                float4 a = p[0], bq = p[1];
                qsd[0]=a.x; qsd[1]=a.y; qsd[2]=a.z; qsd[3]=a.w;
                qsd[4]=bq.x; qsd[5]=bq.y; qsd[6]=bq.z; qsd[7]=bq.w;
            }
            {
                const float4* p = reinterpret_cast<const float4*>(g_qv + (size_t)dst * 24);
                #pragma unroll
                for (int qq = 0; qq < 6; qq++) {
                    float4 v = p[qq];
                    qvd[4*qq]=v.x; qvd[4*qq+1]=v.y; qvd[4*qq+2]=v.z; qvd[4*qq+3]=v.w;
                }
            }
            float t0 = 0.f, t1 = 0.f;
            #pragma unroll
            for (int m = 0; m < 8; m++) {
                float rr = 0.f;
                #pragma unroll
                for (int n = 0; n < 8; n++) rr = fmaf(__ldg(Wd0 + m * 8 + n), ks[n], rr);
                t0 = fmaf(qsd[m], rr, t0);
            }
            #pragma unroll
            for (int m = 0; m < 8; m++) {
                float rr = 0.f;
                #pragma unroll
                for (int n = 0; n < 8; n++) {
                    float dd = qvd[3*m] * kv[n][0] + qvd[3*m+1] * kv[n][1] + qvd[3*m+2] * kv[n][2];
                    rr = fmaf(__ldg(Wd1 + m * 8 + n), dd, rr);
                }
                t1 += rr;
            }
            float logit = (t0 + t1 * i3) * 0.25f;
            float ex = __expf(logit);
            if (active) {
                g_expv[e] = ex;
                atomicAdd(&g_zsum[dst], ex);
                atomicAdd(&g_cnt[dst], 1.f);
            }
        } else {
            // ---- V radial -> g_vbuf ----
            if (active) {
                #pragma unroll
                for (int n = 0; n < 8; n++) g_vbuf[n * EN + e] = Sg[n] * c_s;
                #pragma unroll
                for (int n = 0; n < 8; n++) {
                    g_vbuf[(8 + 3*n + 0) * EN + e] = (T1g[n] * s1x + Tx[n]) * c_v;
                    g_vbuf[(8 + 3*n + 1) * EN + e] = (T1g[n] * s1y + Ty[n]) * c_v;
                    g_vbuf[(8 + 3*n + 2) * EN + e] = (T1g[n] * s1z + Tz[n]) * c_v;
                }
            }
        }
        __syncthreads();   // A reused next radial
    }
}

// ---------------- kernel: normalize + scatter ----------------
__global__ void scatter_kernel(const int* __restrict__ ei, float* __restrict__ out) {
    int e = blockIdx.x * blockDim.x + threadIdx.x;
    if (e >= EN) return;
    int dst = __ldg(ei + EN + e);
    float ex = g_expv[e];
    float zs = g_zsum[dst];
    float c  = g_cnt[dst];
    float alpha = ex * fmaxf(c, 1.f) / zs;
    float attn = sqrtf(fmaxf(alpha, 0.f));
    float* op = out + (size_t)dst * 32;
    #pragma unroll
    for (int k = 0; k < 32; k++)
        atomicAdd(op + k, attn * g_vbuf[k * EN + e]);
}

// ---------------- launcher ----------------
extern "C" void kernel_launch(void* const* d_in, const int* in_sizes, int n_in,
                              void* d_out, int out_size) {
    const float* node_attr = (const float*)d_in[0];
    const int*   ei        = (const int*)  d_in[1];
    const float* edge_attr = (const float*)d_in[2];
    const float* edge_sh   = (const float*)d_in[3];
    const float* Wq0       = (const float*)d_in[4];
    const float* Wq1       = (const float*)d_in[5];
    const float* kW1       = (const float*)d_in[6];
    const float* kW2       = (const float*)d_in[7];
    const float* vW1       = (const float*)d_in[8];
    const float* vW2       = (const float*)d_in[9];
    const float* Wd0       = (const float*)d_in[10];
    const float* Wd1       = (const float*)d_in[11];
    float* out = (float*)d_out;

    static bool attr_set = false;
    if (!attr_set) {
        cudaFuncSetAttribute(edge_mma_kernel,
                             cudaFuncAttributeMaxDynamicSharedMemorySize, SMEM_BYTES);
        attr_set = true;
    }

    w2frag_kernel<<<(2 * 5 * 8 * 8 * 32 + 255) / 256, 256>>>(kW2, vW2);
    zero_kernel<<<(NN * 32 + 255) / 256, 256>>>(out);
    node_kernel<<<(NN + 127) / 128, 128>>>(node_attr, Wq0, Wq1);
    edge_mma_kernel<<<NTILES, TILE, SMEM_BYTES>>>(node_attr, ei, edge_attr, edge_sh,
                                                  kW1, vW1, Wd0, Wd1);
    scatter_kernel<<<(EN + 255) / 256, 256>>>(ei, out);
}